// round 17
// baseline (speedup 1.0000x reference)
#include <cuda_runtime.h>
#include <math.h>

#define M_   24
#define TS_  60
#define NX_  192
#define NY_  192
#define NG_  50
#define T_   50
#define HD_  32   // H*D
#define H_   4
#define D_   8

// Compact tables: setup_kernel -> gather_kernel
__device__ float g_e0[M_ * NG_];     // w*my*(1-fy)
__device__ float g_e1[M_ * NG_];     // w*my*fy
__device__ short g_iy[M_ * NG_];
__device__ int   g_ix[NG_];
__device__ float g_fx[NG_];
__device__ float g_mx[NG_];

// jnp.linspace(0,100,192): delta = 100/191 (f32), endpoint forced exact.
__device__ __forceinline__ float gridx(int k) {
    return (k == NX_ - 1) ? 100.0f : (float)k * (100.0f / 191.0f);
}

__global__ __launch_bounds__(1024)
void setup_kernel(const float* __restrict__ params,
                  const float* __restrict__ src_y,
                  const float* __restrict__ stl,
                  const float* __restrict__ Wq,
                  const float* __restrict__ bq,
                  const float* __restrict__ Wk,
                  const float* __restrict__ bk,
                  const float* __restrict__ lyt_p,
                  const float* __restrict__ cut_p,
                  const float* __restrict__ nit_p)
{
    __shared__ __align__(16) float s_y[M_ * NY_];
    __shared__ float s_Wq[3*HD_], s_Wk[3*HD_], s_bq[HD_], s_bk[HD_], s_Q[HD_];
    __shared__ float s_ly[M_], s_cu[M_], s_ni[M_], s_scale[M_];
    __shared__ float s_logits[M_][H_];
    __shared__ float s_sm[H_][M_];
    __shared__ float s_w[M_];

    const int tid = threadIdx.x;
    const float lyt = __ldg(lyt_p);
    const float t_ly = (lyt - 30.0f) / 90.0f;
    const float t_cu = __ldg(cut_p) / 0.0029f;
    const float t_ni = __ldg(nit_p) / 0.0018f;

    // ---- phase 0: stage inputs ----
    {
        const float4* sy4 = reinterpret_cast<const float4*>(src_y);
        float4* dy4 = reinterpret_cast<float4*>(s_y);
        for (int p = tid; p < (M_ * NY_) / 4; p += 1024)
            dy4[p] = __ldg(sy4 + p);
    }
    if (tid < 3 * HD_) { s_Wq[tid] = __ldg(Wq + tid); s_Wk[tid] = __ldg(Wk + tid); }
    else if (tid >= 128 && tid < 128 + HD_) {
        int k = tid - 128;
        s_bq[k] = __ldg(bq + k); s_bk[k] = __ldg(bk + k);
    }
    else if (tid >= 192 && tid < 192 + M_) {
        int m = tid - 192;
        float lys = __ldg(params + 3*m + 0);
        s_ly[m] = (lys - 30.0f) / 90.0f;
        s_cu[m] = __ldg(params + 3*m + 1) / 0.0029f;
        s_ni[m] = __ldg(params + 3*m + 2) / 0.0018f;
        s_scale[m] = lyt / lys;
    }
    __syncthreads();

    // ---- phase 1: Q vector ----
    if (tid < HD_)
        s_Q[tid] = t_ly*s_Wq[tid] + t_cu*s_Wq[HD_+tid] + t_ni*s_Wq[2*HD_+tid] + s_bq[tid];
    __syncthreads();

    // ---- phase 2: logits (m,h) ----
    if (tid < M_ * H_) {
        int m = tid / H_, h = tid % H_;
        float acc = 0.0f;
        #pragma unroll
        for (int d = 0; d < D_; d++) {
            int k = h*D_ + d;
            float Kv = s_ly[m]*s_Wk[k] + s_cu[m]*s_Wk[HD_+k] + s_ni[m]*s_Wk[2*HD_+k] + s_bk[k];
            acc += Kv * s_Q[k];
        }
        s_logits[m][h] = acc * (1.0f / sqrtf((float)D_));
    }
    __syncthreads();

    // ---- phase 3: softmax per head ----
    if (tid < H_) {
        int h = tid;
        float mx = -1e30f;
        for (int m = 0; m < M_; m++) mx = fmaxf(mx, s_logits[m][h]);
        float s = 0.0f;
        for (int m = 0; m < M_; m++) s += expf(s_logits[m][h] - mx);
        for (int m = 0; m < M_; m++) s_sm[h][m] = expf(s_logits[m][h] - mx) / s;
    }
    __syncthreads();

    // ---- phase 4: weights, warp 0 shfl reductions ----
    if (tid < 32) {
        int m = tid;
        float swv = 0.0f, attn = 0.0f;
        if (m < M_) {
            float d2 = ((s_ly[m]-t_ly)*(s_ly[m]-t_ly) +
                        (s_cu[m]-t_cu)*(s_cu[m]-t_cu) +
                        (s_ni[m]-t_ni)*(s_ni[m]-t_ni)) / (0.2f*0.2f);
            swv = expf(-d2 * 0.5f);
            attn = (s_sm[0][m] + s_sm[1][m] + s_sm[2][m] + s_sm[3][m]) * 0.25f;
        }
        float ssum = swv;
        #pragma unroll
        for (int o = 16; o > 0; o >>= 1) ssum += __shfl_xor_sync(0xffffffff, ssum, o);
        float wa = attn * (swv / (ssum + 1e-12f));
        float wsum = wa;
        #pragma unroll
        for (int o = 16; o > 0; o >>= 1) wsum += __shfl_xor_sync(0xffffffff, wsum, o);
        if (m < M_) s_w[m] = wa / (wsum + 1e-12f);
    }
    __syncthreads();

    // ---- phase 5: tables ----
    if (tid >= 512 && tid < 512 + NG_) {
        int i = tid - 512;
        float q = (i == NG_-1) ? 100.0f : (float)i * (100.0f / 49.0f);
        int lo = 0, hi = NX_;
        while (lo < hi) { int mid = (lo + hi) >> 1; if (gridx(mid) <= q) lo = mid + 1; else hi = mid; }
        int idx = min(max(lo - 1, 0), NX_ - 2);
        float g0 = gridx(idx), g1 = gridx(idx + 1);
        g_ix[i] = idx;
        g_fx[i] = (q - g0) / (g1 - g0);
        g_mx[i] = (q >= 0.0f && q <= 100.0f) ? 1.0f : 0.0f;
    }
    if (tid < 512) {
        for (int p = tid; p < M_ * NG_; p += 512) {
            int m = p / NG_, j = p % NG_;
            float q  = (float)j / 49.0f * lyt;
            float sc = s_scale[m];
            const float* ys = s_y + m * NY_;
            int lo = 0, hi = NY_;
            while (lo < hi) { int mid = (lo + hi) >> 1; if (ys[mid]*sc <= q) lo = mid + 1; else hi = mid; }
            int idx = min(max(lo - 1, 0), NY_ - 2);
            float gy0 = ys[idx] * sc, gy1 = ys[idx + 1] * sc;
            float fy = (q - gy0) / (gy1 - gy0);
            float inb = (q >= ys[0]*sc && q <= ys[NY_-1]*sc) ? 1.0f : 0.0f;
            float wm = s_w[m] * inb;
            g_iy[p] = (short)idx;
            g_e0[p] = wm * (1.0f - fy);
            g_e1[p] = wm * fy;
        }
    }

    cudaTriggerProgrammaticLaunchCompletion();
}

// One block per (f,t,i). Phase A (pre-sync): coalesced float4-stream the 48
// needed rows into shared (addresses need no setup tables). Phase B
// (post-sync): 50 threads combine from shared using the g-tables.
__global__ __launch_bounds__(256)
void gather_kernel(const float* __restrict__ c1,
                   const float* __restrict__ c2,
                   const float* __restrict__ stl,
                   const float* __restrict__ cut_p,
                   const float* __restrict__ nit_p,
                   float* __restrict__ out)
{
    __shared__ __align__(16) float s_rows[2 * M_][NY_];   // 36.9 KB
    __shared__ const float* s_rp[2 * M_];
    __shared__ int s_ixs;

    const int tid = threadIdx.x;
    const int b   = blockIdx.x;            // 0..4999
    const int i   = b % NG_;
    const int t   = (b / NG_) % T_;
    const int f   = b / (T_ * NG_);

    // ---- row pointers: pure arithmetic + stl (no setup tables) ----
    if (tid < 2 * M_) {
        const int m    = tid >> 1;
        const int rsel = tid & 1;
        // ix: searchsorted on uniform x grid (same semantics as setup)
        float q = (i == NG_-1) ? 100.0f : (float)i * (100.0f / 49.0f);
        int lo = 0, hi = NX_;
        while (lo < hi) { int mid = (lo + hi) >> 1; if (gridx(mid) <= q) lo = mid + 1; else hi = mid; }
        int ix = min(max(lo - 1, 0), NX_ - 2);
        if (tid == 0) s_ixs = ix;
        // ti: round-half-even on stl
        float tv = (t == T_-1) ? 200.0f : (float)t * (200.0f / 49.0f);
        float r = rintf(tv / __ldg(stl + m) * (float)(TS_ - 1));
        int ti = min(max((int)r, 0), TS_ - 1);
        const float* __restrict__ base = f ? c2 : c1;
        s_rp[tid] = base + (m * TS_ + ti) * (NX_*NY_) + (ix + rsel) * NY_;
    }
    __syncthreads();

    // ---- phase A: coalesced stream 48 rows x 192 floats into shared ----
    // 2304 float4 over 256 threads = 9 each, fully independent.
    #pragma unroll
    for (int p = tid; p < 2 * M_ * (NY_ / 4); p += 256) {
        const int r = p / (NY_ / 4);
        const int c = p % (NY_ / 4);
        const float4 v = __ldg(reinterpret_cast<const float4*>(s_rp[r]) + c);
        reinterpret_cast<float4*>(&s_rows[r][0])[c] = v;
    }

    // ---- gate on setup tables (stream above overlapped with setup) ----
    cudaGridDependencySynchronize();
    __syncthreads();

    // ---- phase B: 50 threads combine ----
    if (tid < NG_) {
        const int j = tid;
        const float fx  = __ldg(g_fx + i);
        const float fx1 = 1.0f - fx;

        float acc = 0.0f;
        #pragma unroll
        for (int m = 0; m < M_; m++) {
            const int   iy = __ldg(g_iy + m * NG_ + j);
            const float e0 = __ldg(g_e0 + m * NG_ + j);
            const float e1 = __ldg(g_e1 + m * NG_ + j);
            const float* r0 = s_rows[2*m];
            const float* r1 = s_rows[2*m + 1];
            float a00 = r0[iy];
            float a01 = r0[iy + 1];
            float a10 = r1[iy];
            float a11 = r1[iy + 1];
            acc += (a00 * fx1 + a10 * fx) * e0 + (a01 * fx1 + a11 * fx) * e1;
        }
        float v = acc * __ldg(g_mx + i);
        if (f == 0 && j == 0)       v = __ldg(cut_p);
        if (f == 1 && j == NG_ - 1) v = __ldg(nit_p);

        out[((f * T_ + t) * NG_ + i) * NG_ + j] = v;
    }
}

extern "C" void kernel_launch(void* const* d_in, const int* in_sizes, int n_in,
                              void* d_out, int out_size)
{
    const float* c1    = (const float*)d_in[0];
    const float* c2    = (const float*)d_in[1];
    const float* params= (const float*)d_in[2];
    const float* src_y = (const float*)d_in[3];
    const float* stl   = (const float*)d_in[4];
    const float* Wq    = (const float*)d_in[5];
    const float* bq    = (const float*)d_in[6];
    const float* Wk    = (const float*)d_in[7];
    const float* bk    = (const float*)d_in[8];
    const float* lyt   = (const float*)d_in[9];
    const float* cut   = (const float*)d_in[10];
    const float* nit   = (const float*)d_in[11];
    float* out = (float*)d_out;

    setup_kernel<<<1, 1024>>>(params, src_y, stl, Wq, bq, Wk, bk, lyt, cut, nit);

    const int blocks = 2 * T_ * NG_;    // 5000: one per (f,t,i)

    // PDL launch: phase A row-streaming overlaps setup execution.
    cudaLaunchConfig_t cfg = {};
    cfg.gridDim  = dim3((unsigned)blocks, 1, 1);
    cfg.blockDim = dim3(256, 1, 1);
    cfg.dynamicSmemBytes = 0;
    cfg.stream = 0;
    cudaLaunchAttribute attrs[1];
    attrs[0].id = cudaLaunchAttributeProgrammaticStreamSerialization;
    attrs[0].val.programmaticStreamSerializationAllowed = 1;
    cfg.attrs = attrs;
    cfg.numAttrs = 1;
    cudaLaunchKernelEx(&cfg, gather_kernel, c1, c2, stl, cut, nit, out);
}